// round 13
// baseline (speedup 1.0000x reference)
#include <cuda_runtime.h>
#include <cstdint>

#define V      81616
#define VT     81664           // transposed-w padded k extent (mult of 64)
#define BATCH  4096
#define DIM    32
#define SPLITS 18
#define SPAN   4544            // 142*32; last split span 4368 -> 137 stages
#define KC     32
#define NW     192             // decoder column span per CTA

// Scratch (static device globals — allocation-free)
__device__ float g_part[SPLITS * BATCH * DIM];   // split-K partials
__device__ float g_hs[BATCH * DIM];              // sigmoid(hidden)
__device__ float g_wcT[DIM * VT];                // w tf32(rna), transposed [d][k], zero tail

// ---------- helpers ----------
__device__ __forceinline__ void cp16(void* dst_smem, const void* src) {
    unsigned d = (unsigned)__cvta_generic_to_shared(dst_smem);
    asm volatile("cp.async.cg.shared.global [%0], [%1], 16;" :: "r"(d), "l"(src));
}
__device__ __forceinline__ void cp_commit() {
    asm volatile("cp.async.commit_group;");
}
template <int N>
__device__ __forceinline__ void cp_wait() {
    asm volatile("cp.async.wait_group %0;" :: "n"(N));
}
__device__ __forceinline__ uint32_t tf32(float f) {
    uint32_t u;
    asm("cvt.rna.tf32.f32 %0, %1;" : "=r"(u) : "f"(f));
    return u;
}
__device__ __forceinline__ void mma8(float& d0, float& d1, float& d2, float& d3,
                                     uint32_t a0, uint32_t a1, uint32_t a2, uint32_t a3,
                                     uint32_t b0, uint32_t b1) {
    asm("mma.sync.aligned.m16n8k8.row.col.f32.tf32.tf32.f32 "
        "{%0,%1,%2,%3}, {%4,%5,%6,%7}, {%8,%9}, {%0,%1,%2,%3};"
        : "+f"(d0), "+f"(d1), "+f"(d2), "+f"(d3)
        : "r"(a0), "r"(a1), "r"(a2), "r"(a3), "r"(b0), "r"(b1));
}
__device__ __forceinline__ float sig_tanh(float z) {
    float t;
    asm("tanh.approx.f32 %0, %1;" : "=f"(t) : "f"(0.5f * z));
    return fmaf(0.5f, t, 0.5f);
}
__device__ __forceinline__ float sig_exact(float z) {
    return __fdividef(1.0f, 1.0f + __expf(-z));
}
__device__ __forceinline__ uint32_t fb(float f) { return __float_as_uint(f); }

// ---------- kernel 0: transpose + round w -> g_wcT[32][VT], zero tail ----------
__global__ void k_wconvT(const float* __restrict__ w) {
    __shared__ float s[64][33];
    int k0 = blockIdx.x * 64;
    int tid = threadIdx.x; // 256 threads
#pragma unroll
    for (int i = 0; i < 8; i++) {
        int idx = tid + i * 256;
        int r = idx >> 5, d = idx & 31;
        int k = k0 + r;
        s[r][d] = (k < V) ? __uint_as_float(tf32(w[(size_t)k * DIM + d])) : 0.0f;
    }
    __syncthreads();
#pragma unroll
    for (int i = 0; i < 8; i++) {
        int idx = tid + i * 256;
        int d = idx >> 6, c = idx & 63;
        g_wcT[(size_t)d * VT + k0 + c] = s[c][d];
    }
}

// ---------- kernel 1: encoder, k-permuted frags, all LDS.128 (unchanged R12) ----------
__global__ __launch_bounds__(256, 4) void k_encoder(const float* __restrict__ x) {
    __shared__ __align__(16) float xs[2][128 * 32];  // 32 KB
    __shared__ __align__(16) float ws[2][32 * 32];   //  8 KB

    int tid  = threadIdx.x;
    int warp = tid >> 5, lane = tid & 31;
    int l4 = lane >> 2, lm4 = lane & 3;
    int wr0 = warp * 16;
    int row0  = blockIdx.x * 128;
    int split = blockIdx.y;
    int k0    = split * SPAN;
    int kspan = min(SPAN, V - k0);
    int nstg  = (kspan + KC - 1) / KC;

    const size_t XMAX = (size_t)BATCH * V - 4;

    float acc[4][4];
#pragma unroll
    for (int j = 0; j < 4; j++)
#pragma unroll
        for (int c = 0; c < 4; c++) acc[j][c] = 0.0f;

    int wd = tid >> 3, wcc = tid & 7;

    auto stage = [&](int s, int slot) {
        int kb = k0 + s * KC;
#pragma unroll
        for (int i = 0; i < 4; i++) {
            int idx = tid + 256 * i;
            int r = idx >> 3, cc = idx & 7;
            size_t off = (size_t)(row0 + r) * V + kb + (cc << 2);
            if (off > XMAX) off = XMAX;   // finite garbage; matching wT rows are zero
            cp16(&xs[slot][r * 32 + (((cc << 2)) ^ ((r & 1) << 4))], x + off);
        }
        cp16(&ws[slot][wd * 32 + (((wcc << 2)) ^ ((wd & 1) << 4))],
             g_wcT + (size_t)wd * VT + kb + (wcc << 2));
    };

    stage(0, 0);
    cp_commit();

    int pa = (l4 & 1) << 4;
    int caLo = ((lm4 << 2) ^ pa) >> 2;
    int caHi = caLo ^ 4;

#pragma unroll 1
    for (int s = 0; s < nstg; s++) {
        int slot = s & 1;
        if (s + 1 < nstg) {
            stage(s + 1, slot ^ 1);
            cp_commit();
            cp_wait<1>();
        } else {
            cp_commit();
            cp_wait<0>();
        }
        __syncthreads();

        const float4* xrL = (const float4*)&xs[slot][(wr0 + l4) * 32];
        const float4* xrH = (const float4*)&xs[slot][(wr0 + l4 + 8) * 32];
        float4 aL0 = xrL[caLo];
        float4 aL1 = xrL[caHi];
        float4 aH0 = xrH[caLo];
        float4 aH1 = xrH[caHi];

#pragma unroll
        for (int jp = 0; jp < 2; jp++) {
            const float4* br0 = (const float4*)&ws[slot][((jp * 2) * 8 + l4) * 32];
            const float4* br1 = (const float4*)&ws[slot][((jp * 2 + 1) * 8 + l4) * 32];
            float4 b00 = br0[caLo], b01 = br0[caHi];
            float4 b10 = br1[caLo], b11 = br1[caHi];
#pragma unroll
            for (int kk = 0; kk < 4; kk++) {
                uint32_t a0 = fb(((const float*)&aL0)[kk]);
                uint32_t a1 = fb(((const float*)&aH0)[kk]);
                uint32_t a2 = fb(((const float*)&aL1)[kk]);
                uint32_t a3 = fb(((const float*)&aH1)[kk]);
                mma8(acc[jp * 2][0], acc[jp * 2][1], acc[jp * 2][2], acc[jp * 2][3],
                     a0, a1, a2, a3,
                     fb(((const float*)&b00)[kk]), fb(((const float*)&b01)[kk]));
                mma8(acc[jp * 2 + 1][0], acc[jp * 2 + 1][1], acc[jp * 2 + 1][2], acc[jp * 2 + 1][3],
                     a0, a1, a2, a3,
                     fb(((const float*)&b10)[kk]), fb(((const float*)&b11)[kk]));
            }
        }
        __syncthreads();
    }

    float* p = g_part + (size_t)split * (BATCH * DIM)
             + (size_t)(row0 + wr0 + l4) * DIM + lm4 * 2;
#pragma unroll
    for (int j = 0; j < 4; j++) {
        *(float2*)(p + j * 8)            = make_float2(acc[j][0], acc[j][1]);
        *(float2*)(p + 8 * DIM + j * 8)  = make_float2(acc[j][2], acc[j][3]);
    }
}

// ---------- kernel 2: reduce partials + bias + sigmoid (exact) ----------
__global__ void k_hidden(const float* __restrict__ b) {
    int i = blockIdx.x * 256 + threadIdx.x;
    float s = 0.0f;
#pragma unroll
    for (int c = 0; c < SPLITS; c++) s += g_part[(size_t)c * (BATCH * DIM) + i];
    s += b[i & 31];
    g_hs[i] = sig_exact(s);
}

// ---------- kernel 3: decoder, M=256/CTA (w tile staged once), direct stores ----------
// B frags from RAW w (tf32 truncation); hs A-frags cvt.rna per half.
__global__ __launch_bounds__(256, 4) void k_decoder(const float* __restrict__ w,
                                                    float* __restrict__ out) {
    __shared__ __align__(16) float hs_s[128 * 32];   // 16 KB, natural
    __shared__ __align__(16) float wv_s[NW * 32];    // 24 KB, swizzled

    int tid  = threadIdx.x;
    int warp = tid >> 5, lane = tid & 31;
    int l4 = lane >> 2, lm4 = lane & 3;
    int wr0 = warp * 16;
    int m0 = blockIdx.y * 256;
    int n0 = blockIdx.x * NW;

    // stage w tile once (raw bits)
#pragma unroll
    for (int i = 0; i < 6; i++) {
        int idx = tid + 256 * i;
        int vrow = idx >> 3, cc = idx & 7;
        int vs = n0 + vrow;
        if (vs > V - 1) vs = V - 1;
        cp16(&wv_s[vrow * 32 + (((cc << 2)) ^ ((vrow & 1) << 4))],
             w + (size_t)vs * DIM + (cc << 2));
    }
    // stage hs half 0
#pragma unroll
    for (int i = 0; i < 4; i++) {
        int idx = tid + 256 * i;
        int r = idx >> 3, cc = idx & 7;
        cp16(&hs_s[r * 32 + (cc << 2)], g_hs + (size_t)(m0 + r) * DIM + (cc << 2));
    }
    cp_commit();
    cp_wait<0>();
    __syncthreads();

    int jmax = min(NW / 8, (V - n0) >> 3);   // V multiple of 8
    int pa = (l4 & 1) << 4;
    int cbLo = ((lm4 << 2) ^ pa) >> 2;
    int cbHi = cbLo ^ 4;

#pragma unroll 1
    for (int h = 0; h < 2; h++) {
        // A frags for this half (permuted k)
        uint32_t ua[4][4];
        const float* hb = &hs_s[(wr0 + l4) * 32];
        const float* hb8 = hb + 8 * 32;
#pragma unroll
        for (int kk = 0; kk < 4; kk++) {
            ua[kk][0] = tf32(hb[lm4 * 4 + kk]);
            ua[kk][1] = tf32(hb8[lm4 * 4 + kk]);
            ua[kk][2] = tf32(hb[16 + lm4 * 4 + kk]);
            ua[kk][3] = tf32(hb8[16 + lm4 * 4 + kk]);
        }

        float* o0 = out + (size_t)(m0 + h * 128 + wr0 + l4) * V + n0 + lm4 * 2;
        float* o1 = o0 + (size_t)8 * V;

#pragma unroll 2
        for (int j = 0; j < jmax; j++) {
            const float4* br = (const float4*)&wv_s[(j * 8 + l4) * 32];
            float4 b0v = br[cbLo];
            float4 b1v = br[cbHi];
            float d0 = 0.f, d1 = 0.f, d2 = 0.f, d3 = 0.f;
#pragma unroll
            for (int kk = 0; kk < 4; kk++) {
                mma8(d0, d1, d2, d3,
                     ua[kk][0], ua[kk][1], ua[kk][2], ua[kk][3],
                     fb(((const float*)&b0v)[kk]), fb(((const float*)&b1v)[kk]));
            }
            __stcs((float2*)(o0 + j * 8), make_float2(sig_tanh(d0), sig_tanh(d1)));
            __stcs((float2*)(o1 + j * 8), make_float2(sig_tanh(d2), sig_tanh(d3)));
        }

        // restage hs for half 1
        if (h == 0) {
            __syncthreads();
#pragma unroll
            for (int i = 0; i < 4; i++) {
                int idx = tid + 256 * i;
                int r = idx >> 3, cc = idx & 7;
                cp16(&hs_s[r * 32 + (cc << 2)],
                     g_hs + (size_t)(m0 + 128 + r) * DIM + (cc << 2));
            }
            cp_commit();
            cp_wait<0>();
            __syncthreads();
        }
    }
}

extern "C" void kernel_launch(void* const* d_in, const int* in_sizes, int n_in,
                              void* d_out, int out_size) {
    const float* x = (const float*)d_in[0];
    const float* w = (const float*)d_in[1];
    const float* b = (const float*)d_in[2];
    float* out = (float*)d_out;

    k_wconvT<<<VT / 64, 256>>>(w);
    k_encoder<<<dim3(BATCH / 128, SPLITS), 256>>>(x);
    k_hidden<<<(BATCH * DIM) / 256, 256>>>(b);
    k_decoder<<<dim3((V + NW - 1) / NW, BATCH / 256), 256>>>(w, out);
}

// round 14
// speedup vs baseline: 1.0430x; 1.0430x over previous
#include <cuda_runtime.h>
#include <cstdint>

#define V      81616
#define VT     81664           // transposed-w padded k extent (mult of 64)
#define BATCH  4096
#define DIM    32
#define SPLITS 18
#define SPAN   4544            // last split span 4368; stages = ceil(span/64)
#define KC     64              // floats per encoder stage (256 B per row)
#define NW     192             // decoder column span per CTA

// Scratch (static device globals — allocation-free)
__device__ float g_part[SPLITS * BATCH * DIM];   // split-K partials
__device__ float g_hs[BATCH * DIM];              // sigmoid(hidden)
__device__ float g_wcT[DIM * VT];                // w tf32(rna), transposed [d][k], zero tail

// ---------- helpers ----------
__device__ __forceinline__ void cp16(void* dst_smem, const void* src) {
    unsigned d = (unsigned)__cvta_generic_to_shared(dst_smem);
    asm volatile("cp.async.cg.shared.global [%0], [%1], 16;" :: "r"(d), "l"(src));
}
__device__ __forceinline__ void cp_commit() {
    asm volatile("cp.async.commit_group;");
}
template <int N>
__device__ __forceinline__ void cp_wait() {
    asm volatile("cp.async.wait_group %0;" :: "n"(N));
}
__device__ __forceinline__ uint32_t tf32(float f) {
    uint32_t u;
    asm("cvt.rna.tf32.f32 %0, %1;" : "=r"(u) : "f"(f));
    return u;
}
__device__ __forceinline__ void mma8(float& d0, float& d1, float& d2, float& d3,
                                     uint32_t a0, uint32_t a1, uint32_t a2, uint32_t a3,
                                     uint32_t b0, uint32_t b1) {
    asm("mma.sync.aligned.m16n8k8.row.col.f32.tf32.tf32.f32 "
        "{%0,%1,%2,%3}, {%4,%5,%6,%7}, {%8,%9}, {%0,%1,%2,%3};"
        : "+f"(d0), "+f"(d1), "+f"(d2), "+f"(d3)
        : "r"(a0), "r"(a1), "r"(a2), "r"(a3), "r"(b0), "r"(b1));
}
__device__ __forceinline__ float sig_tanh(float z) {
    float t;
    asm("tanh.approx.f32 %0, %1;" : "=f"(t) : "f"(0.5f * z));
    return fmaf(0.5f, t, 0.5f);
}
__device__ __forceinline__ float sig_exact(float z) {
    return __fdividef(1.0f, 1.0f + __expf(-z));
}
__device__ __forceinline__ uint32_t fb(float f) { return __float_as_uint(f); }

// ---------- kernel 0: transpose + round w -> g_wcT[32][VT], zero tail ----------
__global__ void k_wconvT(const float* __restrict__ w) {
    __shared__ float s[64][33];
    int k0 = blockIdx.x * 64;
    int tid = threadIdx.x; // 256 threads
#pragma unroll
    for (int i = 0; i < 8; i++) {
        int idx = tid + i * 256;
        int r = idx >> 5, d = idx & 31;
        int k = k0 + r;
        s[r][d] = (k < V) ? __uint_as_float(tf32(w[(size_t)k * DIM + d])) : 0.0f;
    }
    __syncthreads();
#pragma unroll
    for (int i = 0; i < 8; i++) {
        int idx = tid + i * 256;
        int d = idx >> 6, c = idx & 63;
        g_wcT[(size_t)d * VT + k0 + c] = s[c][d];
    }
}

// ---------- kernel 1: encoder, KC=64 (256B/row/stage), k-permuted LDS.128 frags ----------
// xs/ws rows are 64 floats = two 32-float halves; XOR-16-on-odd-row swizzle per half.
__global__ __launch_bounds__(256, 2) void k_encoder(const float* __restrict__ x) {
    __shared__ __align__(16) float xs[2][128 * 64];  // 64 KB
    __shared__ __align__(16) float ws[2][32 * 64];   // 16 KB

    int tid  = threadIdx.x;
    int warp = tid >> 5, lane = tid & 31;
    int l4 = lane >> 2, lm4 = lane & 3;
    int wr0 = warp * 16;
    int row0  = blockIdx.x * 128;
    int split = blockIdx.y;
    int k0    = split * SPAN;
    int kspan = min(SPAN, V - k0);
    int nstg  = (kspan + KC - 1) / KC;

    const size_t XMAX = (size_t)BATCH * V - 4;

    float acc[4][4];
#pragma unroll
    for (int j = 0; j < 4; j++)
#pragma unroll
        for (int c = 0; c < 4; c++) acc[j][c] = 0.0f;

    auto stage = [&](int s, int slot) {
        int kb = k0 + s * KC;
        // x: 128 rows x 16 chunks = 2048 cp16 -> 8/thread
#pragma unroll
        for (int i = 0; i < 8; i++) {
            int idx = tid + 256 * i;
            int r = idx >> 4, cc = idx & 15;
            size_t off = (size_t)(row0 + r) * V + kb + (cc << 2);
            if (off > XMAX) off = XMAX;   // finite garbage; matching wT entries are zero
            cp16(&xs[slot][r * 64 + (((cc << 2)) ^ ((r & 1) << 4))], x + off);
        }
        // w: 32 rows x 16 chunks = 512 cp16 -> 2/thread (wT zero-padded to VT)
#pragma unroll
        for (int i = 0; i < 2; i++) {
            int idx = tid + 256 * i;
            int wd = idx >> 4, wcc = idx & 15;
            cp16(&ws[slot][wd * 64 + (((wcc << 2)) ^ ((wd & 1) << 4))],
                 g_wcT + (size_t)wd * VT + kb + (wcc << 2));
        }
    };

    stage(0, 0);
    cp_commit();

    int pa = (l4 & 1) << 4;
    int caLo = ((lm4 << 2) ^ pa) >> 2;   // float4 index within a 32-float half
    int caHi = caLo ^ 4;

#pragma unroll 1
    for (int s = 0; s < nstg; s++) {
        int slot = s & 1;
        if (s + 1 < nstg) {
            stage(s + 1, slot ^ 1);
            cp_commit();
            cp_wait<1>();
        } else {
            cp_commit();
            cp_wait<0>();
        }
        __syncthreads();

#pragma unroll
        for (int kh = 0; kh < 2; kh++) {
            const float4* xrL = (const float4*)&xs[slot][(wr0 + l4) * 64 + kh * 32];
            const float4* xrH = (const float4*)&xs[slot][(wr0 + l4 + 8) * 64 + kh * 32];
            float4 aL0 = xrL[caLo];
            float4 aL1 = xrL[caHi];
            float4 aH0 = xrH[caLo];
            float4 aH1 = xrH[caHi];

#pragma unroll
            for (int jp = 0; jp < 2; jp++) {
                const float4* br0 = (const float4*)&ws[slot][((jp * 2) * 8 + l4) * 64 + kh * 32];
                const float4* br1 = (const float4*)&ws[slot][((jp * 2 + 1) * 8 + l4) * 64 + kh * 32];
                float4 b00 = br0[caLo], b01 = br0[caHi];
                float4 b10 = br1[caLo], b11 = br1[caHi];
#pragma unroll
                for (int kk = 0; kk < 4; kk++) {
                    uint32_t a0 = fb(((const float*)&aL0)[kk]);
                    uint32_t a1 = fb(((const float*)&aH0)[kk]);
                    uint32_t a2 = fb(((const float*)&aL1)[kk]);
                    uint32_t a3 = fb(((const float*)&aH1)[kk]);
                    mma8(acc[jp * 2][0], acc[jp * 2][1], acc[jp * 2][2], acc[jp * 2][3],
                         a0, a1, a2, a3,
                         fb(((const float*)&b00)[kk]), fb(((const float*)&b01)[kk]));
                    mma8(acc[jp * 2 + 1][0], acc[jp * 2 + 1][1], acc[jp * 2 + 1][2], acc[jp * 2 + 1][3],
                         a0, a1, a2, a3,
                         fb(((const float*)&b10)[kk]), fb(((const float*)&b11)[kk]));
                }
            }
        }
        __syncthreads();
    }

    float* p = g_part + (size_t)split * (BATCH * DIM)
             + (size_t)(row0 + wr0 + l4) * DIM + lm4 * 2;
#pragma unroll
    for (int j = 0; j < 4; j++) {
        *(float2*)(p + j * 8)            = make_float2(acc[j][0], acc[j][1]);
        *(float2*)(p + 8 * DIM + j * 8)  = make_float2(acc[j][2], acc[j][3]);
    }
}

// ---------- kernel 2: reduce partials + bias + sigmoid (exact) ----------
__global__ void k_hidden(const float* __restrict__ b) {
    int i = blockIdx.x * 256 + threadIdx.x;
    float s = 0.0f;
#pragma unroll
    for (int c = 0; c < SPLITS; c++) s += g_part[(size_t)c * (BATCH * DIM) + i];
    s += b[i & 31];
    g_hs[i] = sig_exact(s);
}

// ---------- kernel 3: decoder, M=512/CTA (w tile staged once), direct stores ----------
__global__ __launch_bounds__(256, 4) void k_decoder(const float* __restrict__ w,
                                                    float* __restrict__ out) {
    __shared__ __align__(16) float hs_s[128 * 32];   // 16 KB, natural
    __shared__ __align__(16) float wv_s[NW * 32];    // 24 KB, swizzled

    int tid  = threadIdx.x;
    int warp = tid >> 5, lane = tid & 31;
    int l4 = lane >> 2, lm4 = lane & 3;
    int wr0 = warp * 16;
    int m0 = blockIdx.y * 512;
    int n0 = blockIdx.x * NW;

    // stage w tile once (raw bits -> tf32 truncation in MMA)
#pragma unroll
    for (int i = 0; i < 6; i++) {
        int idx = tid + 256 * i;
        int vrow = idx >> 3, cc = idx & 7;
        int vs = n0 + vrow;
        if (vs > V - 1) vs = V - 1;
        cp16(&wv_s[vrow * 32 + (((cc << 2)) ^ ((vrow & 1) << 4))],
             w + (size_t)vs * DIM + (cc << 2));
    }
    // stage hs block 0
#pragma unroll
    for (int i = 0; i < 4; i++) {
        int idx = tid + 256 * i;
        int r = idx >> 3, cc = idx & 7;
        cp16(&hs_s[r * 32 + (cc << 2)], g_hs + (size_t)(m0 + r) * DIM + (cc << 2));
    }
    cp_commit();
    cp_wait<0>();
    __syncthreads();

    int jmax = min(NW / 8, (V - n0) >> 3);   // V multiple of 8
    int pa = (l4 & 1) << 4;
    int cbLo = ((lm4 << 2) ^ pa) >> 2;
    int cbHi = cbLo ^ 4;

#pragma unroll 1
    for (int h = 0; h < 4; h++) {
        // A frags for this 128-row block (permuted k)
        uint32_t ua[4][4];
        const float* hb = &hs_s[(wr0 + l4) * 32];
        const float* hb8 = hb + 8 * 32;
#pragma unroll
        for (int kk = 0; kk < 4; kk++) {
            ua[kk][0] = tf32(hb[lm4 * 4 + kk]);
            ua[kk][1] = tf32(hb8[lm4 * 4 + kk]);
            ua[kk][2] = tf32(hb[16 + lm4 * 4 + kk]);
            ua[kk][3] = tf32(hb8[16 + lm4 * 4 + kk]);
        }

        float* o0 = out + (size_t)(m0 + h * 128 + wr0 + l4) * V + n0 + lm4 * 2;
        float* o1 = o0 + (size_t)8 * V;

#pragma unroll 2
        for (int j = 0; j < jmax; j++) {
            const float4* br = (const float4*)&wv_s[(j * 8 + l4) * 32];
            float4 b0v = br[cbLo];
            float4 b1v = br[cbHi];
            float d0 = 0.f, d1 = 0.f, d2 = 0.f, d3 = 0.f;
#pragma unroll
            for (int kk = 0; kk < 4; kk++) {
                mma8(d0, d1, d2, d3,
                     ua[kk][0], ua[kk][1], ua[kk][2], ua[kk][3],
                     fb(((const float*)&b0v)[kk]), fb(((const float*)&b1v)[kk]));
            }
            __stcs((float2*)(o0 + j * 8), make_float2(sig_tanh(d0), sig_tanh(d1)));
            __stcs((float2*)(o1 + j * 8), make_float2(sig_tanh(d2), sig_tanh(d3)));
        }

        // restage hs for next 128-row block
        if (h < 3) {
            __syncthreads();
#pragma unroll
            for (int i = 0; i < 4; i++) {
                int idx = tid + 256 * i;
                int r = idx >> 3, cc = idx & 7;
                cp16(&hs_s[r * 32 + (cc << 2)],
                     g_hs + (size_t)(m0 + (h + 1) * 128 + r) * DIM + (cc << 2));
            }
            cp_commit();
            cp_wait<0>();
            __syncthreads();
        }
    }
}

extern "C" void kernel_launch(void* const* d_in, const int* in_sizes, int n_in,
                              void* d_out, int out_size) {
    const float* x = (const float*)d_in[0];
    const float* w = (const float*)d_in[1];
    const float* b = (const float*)d_in[2];
    float* out = (float*)d_out;

    k_wconvT<<<VT / 64, 256>>>(w);
    k_encoder<<<dim3(BATCH / 128, SPLITS), 256>>>(x);
    k_hidden<<<(BATCH * DIM) / 256, 256>>>(b);
    k_decoder<<<dim3((V + NW - 1) / NW, BATCH / 512), 256>>>(w, out);
}

// round 15
// speedup vs baseline: 1.0962x; 1.0510x over previous
#include <cuda_runtime.h>
#include <cstdint>

#define V      81616
#define VT     81664           // transposed-w padded k extent (mult of 64)
#define BATCH  4096
#define DIM    32
#define SPLITS 18
#define SPAN   4544            // last split span 4368; stages = ceil(span/64)
#define KC     64              // floats per encoder stage (256 B per row)
#define NW     192             // decoder column span per CTA

// Scratch (static device globals — allocation-free)
__device__ float g_part[SPLITS * BATCH * DIM];   // split-K partials
__device__ float g_hs[BATCH * DIM];              // sigmoid(hidden)
__device__ float g_wcT[DIM * VT];                // w tf32(rna), transposed [d][k], zero tail

// ---------- helpers ----------
__device__ __forceinline__ void cp16(void* dst_smem, const void* src) {
    unsigned d = (unsigned)__cvta_generic_to_shared(dst_smem);
    asm volatile("cp.async.cg.shared.global [%0], [%1], 16;" :: "r"(d), "l"(src));
}
__device__ __forceinline__ void cp_commit() {
    asm volatile("cp.async.commit_group;");
}
template <int N>
__device__ __forceinline__ void cp_wait() {
    asm volatile("cp.async.wait_group %0;" :: "n"(N));
}
__device__ __forceinline__ uint32_t tf32(float f) {
    uint32_t u;
    asm("cvt.rna.tf32.f32 %0, %1;" : "=r"(u) : "f"(f));
    return u;
}
__device__ __forceinline__ void mma8(float& d0, float& d1, float& d2, float& d3,
                                     uint32_t a0, uint32_t a1, uint32_t a2, uint32_t a3,
                                     uint32_t b0, uint32_t b1) {
    asm("mma.sync.aligned.m16n8k8.row.col.f32.tf32.tf32.f32 "
        "{%0,%1,%2,%3}, {%4,%5,%6,%7}, {%8,%9}, {%0,%1,%2,%3};"
        : "+f"(d0), "+f"(d1), "+f"(d2), "+f"(d3)
        : "r"(a0), "r"(a1), "r"(a2), "r"(a3), "r"(b0), "r"(b1));
}
__device__ __forceinline__ float sig_tanh(float z) {
    float t;
    asm("tanh.approx.f32 %0, %1;" : "=f"(t) : "f"(0.5f * z));
    return fmaf(0.5f, t, 0.5f);
}
__device__ __forceinline__ float sig_exact(float z) {
    return __fdividef(1.0f, 1.0f + __expf(-z));
}
__device__ __forceinline__ uint32_t fb(float f) { return __float_as_uint(f); }

// ---------- kernel 0: transpose + round w -> g_wcT[32][VT], zero tail ----------
__global__ void k_wconvT(const float* __restrict__ w) {
    __shared__ float s[64][33];
    int k0 = blockIdx.x * 64;
    int tid = threadIdx.x; // 256 threads
#pragma unroll
    for (int i = 0; i < 8; i++) {
        int idx = tid + i * 256;
        int r = idx >> 5, d = idx & 31;
        int k = k0 + r;
        s[r][d] = (k < V) ? __uint_as_float(tf32(w[(size_t)k * DIM + d])) : 0.0f;
    }
    __syncthreads();
#pragma unroll
    for (int i = 0; i < 8; i++) {
        int idx = tid + i * 256;
        int d = idx >> 6, c = idx & 63;
        g_wcT[(size_t)d * VT + k0 + c] = s[c][d];
    }
}

// ---------- kernel 1: encoder, KC=64, k-permuted LDS.128 frags (unchanged R14) ----------
__global__ __launch_bounds__(256, 2) void k_encoder(const float* __restrict__ x) {
    __shared__ __align__(16) float xs[2][128 * 64];  // 64 KB
    __shared__ __align__(16) float ws[2][32 * 64];   // 16 KB

    int tid  = threadIdx.x;
    int warp = tid >> 5, lane = tid & 31;
    int l4 = lane >> 2, lm4 = lane & 3;
    int wr0 = warp * 16;
    int row0  = blockIdx.x * 128;
    int split = blockIdx.y;
    int k0    = split * SPAN;
    int kspan = min(SPAN, V - k0);
    int nstg  = (kspan + KC - 1) / KC;

    const size_t XMAX = (size_t)BATCH * V - 4;

    float acc[4][4];
#pragma unroll
    for (int j = 0; j < 4; j++)
#pragma unroll
        for (int c = 0; c < 4; c++) acc[j][c] = 0.0f;

    auto stage = [&](int s, int slot) {
        int kb = k0 + s * KC;
#pragma unroll
        for (int i = 0; i < 8; i++) {
            int idx = tid + 256 * i;
            int r = idx >> 4, cc = idx & 15;
            size_t off = (size_t)(row0 + r) * V + kb + (cc << 2);
            if (off > XMAX) off = XMAX;   // finite garbage; matching wT entries are zero
            cp16(&xs[slot][r * 64 + (((cc << 2)) ^ ((r & 1) << 4))], x + off);
        }
#pragma unroll
        for (int i = 0; i < 2; i++) {
            int idx = tid + 256 * i;
            int wd = idx >> 4, wcc = idx & 15;
            cp16(&ws[slot][wd * 64 + (((wcc << 2)) ^ ((wd & 1) << 4))],
                 g_wcT + (size_t)wd * VT + kb + (wcc << 2));
        }
    };

    stage(0, 0);
    cp_commit();

    int pa = (l4 & 1) << 4;
    int caLo = ((lm4 << 2) ^ pa) >> 2;
    int caHi = caLo ^ 4;

#pragma unroll 1
    for (int s = 0; s < nstg; s++) {
        int slot = s & 1;
        if (s + 1 < nstg) {
            stage(s + 1, slot ^ 1);
            cp_commit();
            cp_wait<1>();
        } else {
            cp_commit();
            cp_wait<0>();
        }
        __syncthreads();

#pragma unroll
        for (int kh = 0; kh < 2; kh++) {
            const float4* xrL = (const float4*)&xs[slot][(wr0 + l4) * 64 + kh * 32];
            const float4* xrH = (const float4*)&xs[slot][(wr0 + l4 + 8) * 64 + kh * 32];
            float4 aL0 = xrL[caLo];
            float4 aL1 = xrL[caHi];
            float4 aH0 = xrH[caLo];
            float4 aH1 = xrH[caHi];

#pragma unroll
            for (int jp = 0; jp < 2; jp++) {
                const float4* br0 = (const float4*)&ws[slot][((jp * 2) * 8 + l4) * 64 + kh * 32];
                const float4* br1 = (const float4*)&ws[slot][((jp * 2 + 1) * 8 + l4) * 64 + kh * 32];
                float4 b00 = br0[caLo], b01 = br0[caHi];
                float4 b10 = br1[caLo], b11 = br1[caHi];
#pragma unroll
                for (int kk = 0; kk < 4; kk++) {
                    uint32_t a0 = fb(((const float*)&aL0)[kk]);
                    uint32_t a1 = fb(((const float*)&aH0)[kk]);
                    uint32_t a2 = fb(((const float*)&aL1)[kk]);
                    uint32_t a3 = fb(((const float*)&aH1)[kk]);
                    mma8(acc[jp * 2][0], acc[jp * 2][1], acc[jp * 2][2], acc[jp * 2][3],
                         a0, a1, a2, a3,
                         fb(((const float*)&b00)[kk]), fb(((const float*)&b01)[kk]));
                    mma8(acc[jp * 2 + 1][0], acc[jp * 2 + 1][1], acc[jp * 2 + 1][2], acc[jp * 2 + 1][3],
                         a0, a1, a2, a3,
                         fb(((const float*)&b10)[kk]), fb(((const float*)&b11)[kk]));
                }
            }
        }
        __syncthreads();
    }

    float* p = g_part + (size_t)split * (BATCH * DIM)
             + (size_t)(row0 + wr0 + l4) * DIM + lm4 * 2;
#pragma unroll
    for (int j = 0; j < 4; j++) {
        *(float2*)(p + j * 8)            = make_float2(acc[j][0], acc[j][1]);
        *(float2*)(p + 8 * DIM + j * 8)  = make_float2(acc[j][2], acc[j][3]);
    }
}

// ---------- kernel 2: reduce partials + bias + sigmoid (exact) ----------
__global__ void k_hidden(const float* __restrict__ b) {
    int i = blockIdx.x * 256 + threadIdx.x;
    float s = 0.0f;
#pragma unroll
    for (int c = 0; c < SPLITS; c++) s += g_part[(size_t)c * (BATCH * DIM) + i];
    s += b[i & 31];
    g_hs[i] = sig_exact(s);
}

// ---------- kernel 3: decoder, M=256/CTA (proven R13 config), direct stores ----------
// B frags from RAW w (tf32 truncation); hs A-frags cvt.rna per half.
__global__ __launch_bounds__(256, 4) void k_decoder(const float* __restrict__ w,
                                                    float* __restrict__ out) {
    __shared__ __align__(16) float hs_s[128 * 32];   // 16 KB, natural
    __shared__ __align__(16) float wv_s[NW * 32];    // 24 KB, swizzled

    int tid  = threadIdx.x;
    int warp = tid >> 5, lane = tid & 31;
    int l4 = lane >> 2, lm4 = lane & 3;
    int wr0 = warp * 16;
    int m0 = blockIdx.y * 256;
    int n0 = blockIdx.x * NW;

    // stage w tile once (raw bits)
#pragma unroll
    for (int i = 0; i < 6; i++) {
        int idx = tid + 256 * i;
        int vrow = idx >> 3, cc = idx & 7;
        int vs = n0 + vrow;
        if (vs > V - 1) vs = V - 1;
        cp16(&wv_s[vrow * 32 + (((cc << 2)) ^ ((vrow & 1) << 4))],
             w + (size_t)vs * DIM + (cc << 2));
    }
    // stage hs half 0
#pragma unroll
    for (int i = 0; i < 4; i++) {
        int idx = tid + 256 * i;
        int r = idx >> 3, cc = idx & 7;
        cp16(&hs_s[r * 32 + (cc << 2)], g_hs + (size_t)(m0 + r) * DIM + (cc << 2));
    }
    cp_commit();
    cp_wait<0>();
    __syncthreads();

    int jmax = min(NW / 8, (V - n0) >> 3);   // V multiple of 8
    int pa = (l4 & 1) << 4;
    int cbLo = ((lm4 << 2) ^ pa) >> 2;
    int cbHi = cbLo ^ 4;

#pragma unroll 1
    for (int h = 0; h < 2; h++) {
        // A frags for this half (permuted k)
        uint32_t ua[4][4];
        const float* hb = &hs_s[(wr0 + l4) * 32];
        const float* hb8 = hb + 8 * 32;
#pragma unroll
        for (int kk = 0; kk < 4; kk++) {
            ua[kk][0] = tf32(hb[lm4 * 4 + kk]);
            ua[kk][1] = tf32(hb8[lm4 * 4 + kk]);
            ua[kk][2] = tf32(hb[16 + lm4 * 4 + kk]);
            ua[kk][3] = tf32(hb8[16 + lm4 * 4 + kk]);
        }

        float* o0 = out + (size_t)(m0 + h * 128 + wr0 + l4) * V + n0 + lm4 * 2;
        float* o1 = o0 + (size_t)8 * V;

#pragma unroll 2
        for (int j = 0; j < jmax; j++) {
            const float4* br = (const float4*)&wv_s[(j * 8 + l4) * 32];
            float4 b0v = br[cbLo];
            float4 b1v = br[cbHi];
            float d0 = 0.f, d1 = 0.f, d2 = 0.f, d3 = 0.f;
#pragma unroll
            for (int kk = 0; kk < 4; kk++) {
                mma8(d0, d1, d2, d3,
                     ua[kk][0], ua[kk][1], ua[kk][2], ua[kk][3],
                     fb(((const float*)&b0v)[kk]), fb(((const float*)&b1v)[kk]));
            }
            __stcs((float2*)(o0 + j * 8), make_float2(sig_tanh(d0), sig_tanh(d1)));
            __stcs((float2*)(o1 + j * 8), make_float2(sig_tanh(d2), sig_tanh(d3)));
        }

        // restage hs for half 1
        if (h == 0) {
            __syncthreads();
#pragma unroll
            for (int i = 0; i < 4; i++) {
                int idx = tid + 256 * i;
                int r = idx >> 3, cc = idx & 7;
                cp16(&hs_s[r * 32 + (cc << 2)],
                     g_hs + (size_t)(m0 + 128 + r) * DIM + (cc << 2));
            }
            cp_commit();
            cp_wait<0>();
            __syncthreads();
        }
    }
}

extern "C" void kernel_launch(void* const* d_in, const int* in_sizes, int n_in,
                              void* d_out, int out_size) {
    const float* x = (const float*)d_in[0];
    const float* w = (const float*)d_in[1];
    const float* b = (const float*)d_in[2];
    float* out = (float*)d_out;

    k_wconvT<<<VT / 64, 256>>>(w);
    k_encoder<<<dim3(BATCH / 128, SPLITS), 256>>>(x);
    k_hidden<<<(BATCH * DIM) / 256, 256>>>(b);
    k_decoder<<<dim3((V + NW - 1) / NW, BATCH / 256), 256>>>(w, out);
}